// round 13
// baseline (speedup 1.0000x reference)
#include <cuda_runtime.h>
#include <cuda_bf16.h>
#include <cstdint>

// ---------------------------------------------------------------------------
// ManifoldMatchingLoss — HMMA (mma.sync bf16, 2-term split) Gram + fused
// rows/softmax/KL/colsum. 2 launches, graph-capturable, allocation-free.
// NOTE: no tcgen05 anywhere — the harness lowers via compute_103 PTX which
// rejects sm_103a-only instructions. mma.sync/ldmatrix are target-agnostic.
//   K1 gram_mma (192 blocks): split-K 128x128 Gram partial via
//      mma.sync.m16n8k16 bf16: G = hi*hi' + hi*lo' + lo*hi' (fp32 accum).
//      Emits partial tile + diagonal side-channel (bit-identical values).
//   K2 rows_colsum (128 blocks): block i reduces row i + norms (same order as
//      diag channel -> exact 0 diagonal), log_softmax both, KL row; the last
//      block to finish does the deterministic column sum -> out, resets ctr.
// ---------------------------------------------------------------------------

#define B_N   128
#define D_F   8192          // image: 64*128
#define D_G   4096          // lang:  32*128
#define CK    64            // K columns per split block
#define S_F   (D_F / CK)    // 128 splits (image)
#define S_G   (D_G / CK)    // 64 splits (lang)
#define NBLK  (S_F + S_G)   // 192

__device__ float g_GfPart[S_F * B_N * B_N];   // 8 MB
__device__ float g_GgPart[S_G * B_N * B_N];   // 4 MB
__device__ float g_diagF[S_F * B_N];
__device__ float g_diagG[S_G * B_N];
__device__ float g_kl[B_N * B_N];
__device__ unsigned int g_sync;               // zero-init; reset by last block

#define SW128(o)  ((o) ^ (((o) >> 3) & 0x70))

// ---- helpers ---------------------------------------------------------------
__device__ __forceinline__ uint32_t smem_u32(const void* p) {
    uint32_t a;
    asm("{ .reg .u64 t; cvta.to.shared.u64 t, %1; cvt.u32.u64 %0, t; }"
        : "=r"(a) : "l"(p));
    return a;
}
__device__ __forceinline__ uint32_t cvt_bf16x2(float lo_val, float hi_val) {
    uint32_t r;   // lo_val -> low half (lower address), hi_val -> high half
    asm("cvt.rn.bf16x2.f32 %0, %1, %2;" : "=r"(r) : "f"(hi_val), "f"(lo_val));
    return r;
}
__device__ __forceinline__ void ldm4(uint32_t* r, uint32_t addr) {
    asm volatile("ldmatrix.sync.aligned.m8n8.x4.shared.b16 {%0,%1,%2,%3}, [%4];"
                 : "=r"(r[0]), "=r"(r[1]), "=r"(r[2]), "=r"(r[3]) : "r"(addr));
}
__device__ __forceinline__ void mma_bf16(float* c, const uint32_t* a,
                                         const uint32_t* b) {
    asm volatile(
        "mma.sync.aligned.m16n8k16.row.col.f32.bf16.bf16.f32 "
        "{%0,%1,%2,%3}, {%4,%5,%6,%7}, {%8,%9}, {%0,%1,%2,%3};"
        : "+f"(c[0]), "+f"(c[1]), "+f"(c[2]), "+f"(c[3])
        : "r"(a[0]), "r"(a[1]), "r"(a[2]), "r"(a[3]), "r"(b[0]), "r"(b[1]));
}

// ---------------------------------------------------------------------------
// Kernel 1: HMMA split-K Gram. One block per (tensor, split).
// 8 warps; warp w computes rows [16w, 16w+16) x all 128 cols.
// ---------------------------------------------------------------------------
__global__ __launch_bounds__(256)
void gram_mma(const float* __restrict__ Fm, const float* __restrict__ Gm) {
    __shared__ __align__(1024) uint8_t sHIb[128 * 128];   // 128 rows x 64 bf16
    __shared__ __align__(1024) uint8_t sLOb[128 * 128];
    const uint32_t sHI = smem_u32(sHIb);
    const uint32_t sLO = smem_u32(sLOb);

    const int bx = blockIdx.x;
    const int t  = threadIdx.x;

    const float* src;
    int D, split;
    float* part;
    float* diag;
    if (bx < S_F) {
        split = bx;        src = Fm; D = D_F;
        part = g_GfPart + (size_t)split * (B_N * B_N);
        diag = g_diagF + split * B_N;
    } else {
        split = bx - S_F;  src = Gm; D = D_G;
        part = g_GgPart + (size_t)split * (B_N * B_N);
        diag = g_diagG + split * B_N;
    }

    // ---- load fp32 chunk, split into bf16 hi/lo, store swizzled ----
    {
        const int row  = t >> 1;            // 0..127
        const int half = t & 1;             // 32-col half
        const float* p = src + (size_t)row * D + split * CK + half * 32;
#pragma unroll
        for (int i = 0; i < 4; i++) {       // 8 floats per iter
            float4 va = *(const float4*)(p + i * 8);
            float4 vb = *(const float4*)(p + i * 8 + 4);
            float f[8] = {va.x, va.y, va.z, va.w, vb.x, vb.y, vb.z, vb.w};
            uint32_t hi[4], lo[4];
#pragma unroll
            for (int q = 0; q < 4; q++) {
                float a = f[2 * q], b = f[2 * q + 1];
                hi[q] = cvt_bf16x2(a, b);
                float ra = a - __bfloat162float(__float2bfloat16(a));
                float rb = b - __bfloat162float(__float2bfloat16(b));
                lo[q] = cvt_bf16x2(ra, rb);
            }
            uint32_t off = SW128((uint32_t)(row * 128 + (half * 32 + i * 8) * 2));
            *(uint4*)(sHIb + off) = make_uint4(hi[0], hi[1], hi[2], hi[3]);
            *(uint4*)(sLOb + off) = make_uint4(lo[0], lo[1], lo[2], lo[3]);
        }
    }
    __syncthreads();

    // ---- MMA mainloop ----
    const int w    = t >> 5;
    const int lane = t & 31;
    const int row0 = w * 16;

    float acc[16][4];
#pragma unroll
    for (int i = 0; i < 16; i++)
#pragma unroll
        for (int q = 0; q < 4; q++) acc[i][q] = 0.f;

    // A frag addr (row-major 16x16):  r0 rows0-7/k0-7, r1 rows8-15/k0-7,
    //                                 r2 rows0-7/k8-15, r3 rows8-15/k8-15
    const int arow = row0 + (lane & 7) + ((lane >> 3) & 1) * 8;
    const int akb  = ((lane >> 4) & 1) * 16;
    // B frag addr (col-major 16x8 pair): r0 n0-7/k0-7, r1 n0-7/k8-15,
    //                                    r2 n8-15/k0-7, r3 n8-15/k8-15
    const int brow = (lane & 7) + ((lane >> 4) & 1) * 8;
    const int bkb  = ((lane >> 3) & 1) * 16;

#pragma unroll
    for (int kc = 0; kc < 4; kc++) {        // K=16 bf16 per chunk
        const int kbase = kc * 32;          // bytes
        uint32_t ahi[4], alo[4];
        {
            uint32_t aoff = SW128((uint32_t)(arow * 128 + kbase + akb));
            ldm4(ahi, sHI + aoff);
            ldm4(alo, sLO + aoff);
        }
#pragma unroll
        for (int t2 = 0; t2 < 8; t2++) {    // two 8-col tiles per iter
            uint32_t bhi[4], blo[4];
            uint32_t boff = SW128((uint32_t)((t2 * 16 + brow) * 128 + kbase + bkb));
            ldm4(bhi, sHI + boff);
            ldm4(blo, sLO + boff);

            mma_bf16(acc[2 * t2 + 0], ahi, &bhi[0]);
            mma_bf16(acc[2 * t2 + 0], ahi, &blo[0]);
            mma_bf16(acc[2 * t2 + 0], alo, &bhi[0]);

            mma_bf16(acc[2 * t2 + 1], ahi, &bhi[2]);
            mma_bf16(acc[2 * t2 + 1], ahi, &blo[2]);
            mma_bf16(acc[2 * t2 + 1], alo, &bhi[2]);
        }
    }

    // ---- epilogue: fragment -> gmem partial (+ diagonal side-channel) ----
    // c0=(g,col) c1=(g,col+1) c2=(g+8,col) c3=(g+8,col+1), col = tile*8+tg*2
    {
        const int g  = lane >> 2;
        const int tg = lane & 3;
        const int ra = row0 + g;
        const int rb = row0 + g + 8;
#pragma unroll
        for (int tile = 0; tile < 16; tile++) {
            const int col = tile * 8 + tg * 2;
            *(float2*)(part + ra * B_N + col) = make_float2(acc[tile][0], acc[tile][1]);
            *(float2*)(part + rb * B_N + col) = make_float2(acc[tile][2], acc[tile][3]);
            if (ra == col)          diag[ra] = acc[tile][0];
            else if (ra == col + 1) diag[ra] = acc[tile][1];
            if (rb == col)          diag[rb] = acc[tile][2];
            else if (rb == col + 1) diag[rb] = acc[tile][3];
        }
    }
}

// ---- fixed-order block reduction over 256 threads (8 warps) ---------------
__device__ __forceinline__ float blkReduce256(float v, bool domax, float* sbuf) {
#pragma unroll
    for (int o = 16; o > 0; o >>= 1) {
        float oth = __shfl_xor_sync(0xffffffffu, v, o);
        v = domax ? fmaxf(v, oth) : (v + oth);
    }
    if ((threadIdx.x & 31) == 0) sbuf[threadIdx.x >> 5] = v;
    __syncthreads();
    float r;
    if (domax) r = fmaxf(fmaxf(fmaxf(sbuf[0], sbuf[1]), fmaxf(sbuf[2], sbuf[3])),
                         fmaxf(fmaxf(sbuf[4], sbuf[5]), fmaxf(sbuf[6], sbuf[7])));
    else       r = ((sbuf[0] + sbuf[1]) + (sbuf[2] + sbuf[3])) +
                   ((sbuf[4] + sbuf[5]) + (sbuf[6] + sbuf[7]));
    __syncthreads();
    return r;
}

// ---------------------------------------------------------------------------
// Kernel 2: block i -> row i (reduce partials + norms, softmax, KL); the LAST
// block to finish performs the deterministic column sum and resets g_sync.
// ---------------------------------------------------------------------------
__global__ __launch_bounds__(256)
void rows_colsum(const float* __restrict__ tptr, float* __restrict__ out) {
    __shared__ float sC[4][2][B_N];
    __shared__ float sb[8];
    __shared__ float sNF[B_N];
    __shared__ float sNG[B_N];
    __shared__ unsigned int s_rank;

    const int i = blockIdx.x;
    const int t = threadIdx.x;
    const int j = t & 127;
    const int h = t >> 7;                  // split half 0/1
    const float eT = expf(tptr[0]);

    // Same split partition + accumulation order for gram-row and norm sums
    // -> at j == i the values are bitwise equal -> diagonal of sq is exactly 0.
    float gf = 0.f, nf = 0.f;
    {
        const float* pr = g_GfPart + (size_t)(h * 64) * (B_N * B_N) + i * B_N + j;
        const float* pd = g_diagF + (h * 64) * B_N + j;
#pragma unroll 16
        for (int s = 0; s < 64; s++) gf += pr[(size_t)s * (B_N * B_N)];
#pragma unroll 16
        for (int s = 0; s < 64; s++) nf += pd[s * B_N];
    }
    float gg = 0.f, ng = 0.f;
    {
        const float* pr = g_GgPart + (size_t)(h * 32) * (B_N * B_N) + i * B_N + j;
        const float* pd = g_diagG + (h * 32) * B_N + j;
#pragma unroll 16
        for (int s = 0; s < 32; s++) gg += pr[(size_t)s * (B_N * B_N)];
#pragma unroll 16
        for (int s = 0; s < 32; s++) ng += pd[s * B_N];
    }
    sC[0][h][j] = gf;  sC[1][h][j] = nf;
    sC[2][h][j] = gg;  sC[3][h][j] = ng;
    __syncthreads();
    const float GF  = sC[0][0][j] + sC[0][1][j];
    const float NFj = sC[1][0][j] + sC[1][1][j];
    const float GG  = sC[2][0][j] + sC[2][1][j];
    const float NGj = sC[3][0][j] + sC[3][1][j];
    if (h == 0) { sNF[j] = NFj; sNG[j] = NGj; }
    __syncthreads();
    const float NFi = sNF[i];
    const float NGi = sNG[i];

    float sqf = (NFi + NFj) - 2.0f * GF;   // exactly 0 when j == i
    float sqg = (NGi + NGj) - 2.0f * GG;
    float df = (sqf > 0.f) ? sqrtf(sqf) : 0.f;
    float dg = (sqg > 0.f) ? sqrtf(sqg) : 0.f;
    float pf = -df * eT;
    float pg = -dg * eT;

    float mf = blkReduce256(pf, true, sb);
    float sf = blkReduce256((h == 0) ? expf(pf - mf) : 0.f, false, sb);
    float mg = blkReduce256(pg, true, sb);
    float sg = blkReduce256((h == 0) ? expf(pg - mg) : 0.f, false, sb);

    if (h == 0) {
        float af = pf - (mf + logf(sf));
        float ag = pg - (mg + logf(sg));
        g_kl[i * B_N + j] = expf(ag) * (ag - af);
    }

    // last-block-does-colsum (threadFenceReduction pattern; deterministic)
    __threadfence();
    __syncthreads();
    if (t == 0) s_rank = atomicAdd(&g_sync, 1u);
    __syncthreads();
    if (s_rank == B_N - 1) {
        __threadfence();                   // acquire: all kl rows visible
        float s = 0.f;
#pragma unroll 16
        for (int k = 0; k < 64; k++)
            s += g_kl[(h * 64 + k) * B_N + j];
        sC[0][h][j] = s;
        __syncthreads();
        if (h == 0) out[j] = sC[0][0][j] + sC[0][1][j];
        if (t == 0) g_sync = 0u;           // reset for next graph replay
    }
}

// ---------------------------------------------------------------------------
extern "C" void kernel_launch(void* const* d_in, const int* in_sizes, int n_in,
                              void* d_out, int out_size) {
    const float* img = nullptr;
    const float* lng = nullptr;
    const float* tmp = nullptr;
    for (int i = 0; i < n_in; i++) {
        if (in_sizes[i] == B_N * D_F)      img = (const float*)d_in[i];
        else if (in_sizes[i] == B_N * D_G) lng = (const float*)d_in[i];
        else if (in_sizes[i] == 1)         tmp = (const float*)d_in[i];
    }
    if (!img) img = (const float*)d_in[0];
    if (!lng) lng = (const float*)d_in[1];
    if (!tmp) tmp = (const float*)d_in[2];

    gram_mma<<<NBLK, 256>>>(img, lng);
    rows_colsum<<<B_N, 256>>>(tmp, (float*)d_out);
}

// round 14
// speedup vs baseline: 1.7207x; 1.7207x over previous
#include <cuda_runtime.h>
#include <cuda_bf16.h>
#include <cstdint>

// ---------------------------------------------------------------------------
// ManifoldMatchingLoss — HMMA (mma.sync bf16, 2-term split) Gram + fused
// rows/softmax/KL/colsum. 2 launches, graph-capturable, allocation-free.
//   K1 gram_mma (96 blocks): split-K (CK=128, two K=64 passes) 128x128 Gram
//      partial via mma.sync.m16n8k16 bf16: G = hi*hi' + hi*lo' + lo*hi'.
//      Emits partial tile + diagonal side-channel (bit-identical values).
//   K2 rows_colsum (128 blocks x 512): block i reduces row i + norms (same
//      partition/order as diag channel -> exact 0 diagonal), log_softmax both,
//      KL row; last block to finish does the column sum -> out, resets ctr.
// ---------------------------------------------------------------------------

#define B_N   128
#define D_F   8192          // image: 64*128
#define D_G   4096          // lang:  32*128
#define CK    128           // K columns per split block (2 passes of 64)
#define S_F   (D_F / CK)    // 64 splits (image)
#define S_G   (D_G / CK)    // 32 splits (lang)
#define NBLK  (S_F + S_G)   // 96

__device__ float g_GfPart[S_F * B_N * B_N];   // 4 MB
__device__ float g_GgPart[S_G * B_N * B_N];   // 2 MB
__device__ float g_diagF[S_F * B_N];
__device__ float g_diagG[S_G * B_N];
__device__ float g_kl[B_N * B_N];
__device__ unsigned int g_sync;               // zero-init; reset by last block

#define SW128(o)  ((o) ^ (((o) >> 3) & 0x70))

// ---- helpers ---------------------------------------------------------------
__device__ __forceinline__ uint32_t smem_u32(const void* p) {
    uint32_t a;
    asm("{ .reg .u64 t; cvta.to.shared.u64 t, %1; cvt.u32.u64 %0, t; }"
        : "=r"(a) : "l"(p));
    return a;
}
__device__ __forceinline__ uint32_t cvt_bf16x2(float lo_val, float hi_val) {
    uint32_t r;   // lo_val -> low half (lower address), hi_val -> high half
    asm("cvt.rn.bf16x2.f32 %0, %1, %2;" : "=r"(r) : "f"(hi_val), "f"(lo_val));
    return r;
}
__device__ __forceinline__ void ldm4(uint32_t* r, uint32_t addr) {
    asm volatile("ldmatrix.sync.aligned.m8n8.x4.shared.b16 {%0,%1,%2,%3}, [%4];"
                 : "=r"(r[0]), "=r"(r[1]), "=r"(r[2]), "=r"(r[3]) : "r"(addr));
}
__device__ __forceinline__ void mma_bf16(float* c, const uint32_t* a,
                                         const uint32_t* b) {
    asm volatile(
        "mma.sync.aligned.m16n8k16.row.col.f32.bf16.bf16.f32 "
        "{%0,%1,%2,%3}, {%4,%5,%6,%7}, {%8,%9}, {%0,%1,%2,%3};"
        : "+f"(c[0]), "+f"(c[1]), "+f"(c[2]), "+f"(c[3])
        : "r"(a[0]), "r"(a[1]), "r"(a[2]), "r"(a[3]), "r"(b[0]), "r"(b[1]));
}

// ---------------------------------------------------------------------------
// Kernel 1: HMMA split-K Gram. One block per (tensor, split of 128 K-cols).
// Two passes of K=64 through 32 KB smem; 8 warps, warp w owns rows [16w,16w+16).
// ---------------------------------------------------------------------------
__global__ __launch_bounds__(256)
void gram_mma(const float* __restrict__ Fm, const float* __restrict__ Gm) {
    __shared__ __align__(1024) uint8_t sHIb[128 * 128];   // 128 rows x 64 bf16
    __shared__ __align__(1024) uint8_t sLOb[128 * 128];
    const uint32_t sHI = smem_u32(sHIb);
    const uint32_t sLO = smem_u32(sLOb);

    const int bx = blockIdx.x;
    const int t  = threadIdx.x;

    const float* src;
    int D, split;
    float* part;
    float* diag;
    if (bx < S_F) {
        split = bx;        src = Fm; D = D_F;
        part = g_GfPart + (size_t)split * (B_N * B_N);
        diag = g_diagF + split * B_N;
    } else {
        split = bx - S_F;  src = Gm; D = D_G;
        part = g_GgPart + (size_t)split * (B_N * B_N);
        diag = g_diagG + split * B_N;
    }

    const int w    = t >> 5;
    const int lane = t & 31;
    const int row0 = w * 16;

    float acc[16][4];
#pragma unroll
    for (int i = 0; i < 16; i++)
#pragma unroll
        for (int q = 0; q < 4; q++) acc[i][q] = 0.f;

    // A frag (row-major 16x16): r0 rows0-7/k0-7, r1 rows8-15/k0-7,
    //                           r2 rows0-7/k8-15, r3 rows8-15/k8-15
    const int arow = row0 + (lane & 7) + ((lane >> 3) & 1) * 8;
    const int akb  = ((lane >> 4) & 1) * 16;
    // B frag (col-major 16x8 pair): r0 n0-7/k0-7, r1 n0-7/k8-15,
    //                               r2 n8-15/k0-7, r3 n8-15/k8-15
    const int brow = (lane & 7) + ((lane >> 4) & 1) * 8;
    const int bkb  = ((lane >> 3) & 1) * 16;

#pragma unroll
    for (int pass = 0; pass < CK / 64; pass++) {
        // ---- load fp32 K=64 chunk, split into bf16 hi/lo, store swizzled ----
        {
            const int row  = t >> 1;            // 0..127
            const int half = t & 1;             // 32-col half
            const float* p = src + (size_t)row * D + split * CK + pass * 64
                             + half * 32;
#pragma unroll
            for (int i = 0; i < 4; i++) {       // 8 floats per iter
                float4 va = *(const float4*)(p + i * 8);
                float4 vb = *(const float4*)(p + i * 8 + 4);
                float f[8] = {va.x, va.y, va.z, va.w, vb.x, vb.y, vb.z, vb.w};
                uint32_t hi[4], lo[4];
#pragma unroll
                for (int q = 0; q < 4; q++) {
                    float a = f[2 * q], b = f[2 * q + 1];
                    hi[q] = cvt_bf16x2(a, b);
                    float ra = a - __bfloat162float(__float2bfloat16(a));
                    float rb = b - __bfloat162float(__float2bfloat16(b));
                    lo[q] = cvt_bf16x2(ra, rb);
                }
                uint32_t off = SW128((uint32_t)(row * 128 + (half * 32 + i * 8) * 2));
                *(uint4*)(sHIb + off) = make_uint4(hi[0], hi[1], hi[2], hi[3]);
                *(uint4*)(sLOb + off) = make_uint4(lo[0], lo[1], lo[2], lo[3]);
            }
        }
        __syncthreads();

        // ---- MMA mainloop over this K=64 chunk ----
#pragma unroll
        for (int kc = 0; kc < 4; kc++) {        // K=16 bf16 per sub-chunk
            const int kbase = kc * 32;          // bytes
            uint32_t ahi[4], alo[4];
            {
                uint32_t aoff = SW128((uint32_t)(arow * 128 + kbase + akb));
                ldm4(ahi, sHI + aoff);
                ldm4(alo, sLO + aoff);
            }
#pragma unroll
            for (int t2 = 0; t2 < 8; t2++) {    // two 8-col tiles per iter
                uint32_t bhi[4], blo[4];
                uint32_t boff = SW128((uint32_t)((t2 * 16 + brow) * 128 + kbase + bkb));
                ldm4(bhi, sHI + boff);
                ldm4(blo, sLO + boff);

                mma_bf16(acc[2 * t2 + 0], ahi, &bhi[0]);
                mma_bf16(acc[2 * t2 + 0], ahi, &blo[0]);
                mma_bf16(acc[2 * t2 + 0], alo, &bhi[0]);

                mma_bf16(acc[2 * t2 + 1], ahi, &bhi[2]);
                mma_bf16(acc[2 * t2 + 1], ahi, &blo[2]);
                mma_bf16(acc[2 * t2 + 1], alo, &bhi[2]);
            }
        }
        __syncthreads();   // smem reads done before next pass overwrites
    }

    // ---- epilogue: fragment -> gmem partial (+ diagonal side-channel) ----
    // c0=(g,col) c1=(g,col+1) c2=(g+8,col) c3=(g+8,col+1), col = tile*8+tg*2
    {
        const int g  = lane >> 2;
        const int tg = lane & 3;
        const int ra = row0 + g;
        const int rb = row0 + g + 8;
#pragma unroll
        for (int tile = 0; tile < 16; tile++) {
            const int col = tile * 8 + tg * 2;
            *(float2*)(part + ra * B_N + col) = make_float2(acc[tile][0], acc[tile][1]);
            *(float2*)(part + rb * B_N + col) = make_float2(acc[tile][2], acc[tile][3]);
            if (ra == col)          diag[ra] = acc[tile][0];
            else if (ra == col + 1) diag[ra] = acc[tile][1];
            if (rb == col)          diag[rb] = acc[tile][2];
            else if (rb == col + 1) diag[rb] = acc[tile][3];
        }
    }
}

// ---- fixed-order block reduction over 512 threads (16 warps) --------------
__device__ __forceinline__ float blkReduce512(float v, bool domax, float* sbuf) {
#pragma unroll
    for (int o = 16; o > 0; o >>= 1) {
        float oth = __shfl_xor_sync(0xffffffffu, v, o);
        v = domax ? fmaxf(v, oth) : (v + oth);
    }
    if ((threadIdx.x & 31) == 0) sbuf[threadIdx.x >> 5] = v;
    __syncthreads();
    float r;
    if (domax) {
        r = fmaxf(fmaxf(fmaxf(sbuf[0], sbuf[1]), fmaxf(sbuf[2], sbuf[3])),
                  fmaxf(fmaxf(sbuf[4], sbuf[5]), fmaxf(sbuf[6], sbuf[7])));
        float r2 = fmaxf(fmaxf(fmaxf(sbuf[8], sbuf[9]), fmaxf(sbuf[10], sbuf[11])),
                         fmaxf(fmaxf(sbuf[12], sbuf[13]), fmaxf(sbuf[14], sbuf[15])));
        r = fmaxf(r, r2);
    } else {
        float a = ((sbuf[0] + sbuf[1]) + (sbuf[2] + sbuf[3])) +
                  ((sbuf[4] + sbuf[5]) + (sbuf[6] + sbuf[7]));
        float b = ((sbuf[8] + sbuf[9]) + (sbuf[10] + sbuf[11])) +
                  ((sbuf[12] + sbuf[13]) + (sbuf[14] + sbuf[15]));
        r = a + b;
    }
    __syncthreads();
    return r;
}

// ---------------------------------------------------------------------------
// Kernel 2: block i -> row i (reduce partials + norms, softmax, KL); the LAST
// block to finish performs the deterministic column sum and resets g_sync.
// 512 threads: h in 0..3 slices the splits (F: 16 each, G: 8 each).
// ---------------------------------------------------------------------------
__global__ __launch_bounds__(512)
void rows_colsum(const float* __restrict__ tptr, float* __restrict__ out) {
    __shared__ float sC[4][4][B_N];
    __shared__ float sb[16];
    __shared__ float sNF[B_N];
    __shared__ float sNG[B_N];
    __shared__ unsigned int s_rank;

    const int i = blockIdx.x;
    const int t = threadIdx.x;
    const int j = t & 127;
    const int h = t >> 7;                  // split slice 0..3
    const float eT = expf(tptr[0]);

    // Same split partition + accumulation order for gram-row and norm sums
    // -> at j == i the values are bitwise equal -> diagonal of sq is exactly 0.
    float gf = 0.f, nf = 0.f;
    {
        const float* pr = g_GfPart + (size_t)(h * 16) * (B_N * B_N) + i * B_N + j;
        const float* pd = g_diagF + (h * 16) * B_N + j;
#pragma unroll
        for (int s = 0; s < 16; s++) gf += pr[(size_t)s * (B_N * B_N)];
#pragma unroll
        for (int s = 0; s < 16; s++) nf += pd[s * B_N];
    }
    float gg = 0.f, ng = 0.f;
    {
        const float* pr = g_GgPart + (size_t)(h * 8) * (B_N * B_N) + i * B_N + j;
        const float* pd = g_diagG + (h * 8) * B_N + j;
#pragma unroll
        for (int s = 0; s < 8; s++) gg += pr[(size_t)s * (B_N * B_N)];
#pragma unroll
        for (int s = 0; s < 8; s++) ng += pd[s * B_N];
    }
    sC[0][h][j] = gf;  sC[1][h][j] = nf;
    sC[2][h][j] = gg;  sC[3][h][j] = ng;
    __syncthreads();
    const float GF  = (sC[0][0][j] + sC[0][1][j]) + (sC[0][2][j] + sC[0][3][j]);
    const float NFj = (sC[1][0][j] + sC[1][1][j]) + (sC[1][2][j] + sC[1][3][j]);
    const float GG  = (sC[2][0][j] + sC[2][1][j]) + (sC[2][2][j] + sC[2][3][j]);
    const float NGj = (sC[3][0][j] + sC[3][1][j]) + (sC[3][2][j] + sC[3][3][j]);
    if (h == 0) { sNF[j] = NFj; sNG[j] = NGj; }
    __syncthreads();
    const float NFi = sNF[i];
    const float NGi = sNG[i];

    float sqf = (NFi + NFj) - 2.0f * GF;   // exactly 0 when j == i
    float sqg = (NGi + NGj) - 2.0f * GG;
    float df = (sqf > 0.f) ? sqrtf(sqf) : 0.f;
    float dg = (sqg > 0.f) ? sqrtf(sqg) : 0.f;
    float pf = -df * eT;
    float pg = -dg * eT;

    float mf = blkReduce512(pf, true, sb);                        // max idempotent
    float sf = blkReduce512((h == 0) ? expf(pf - mf) : 0.f, false, sb);
    float mg = blkReduce512(pg, true, sb);
    float sg = blkReduce512((h == 0) ? expf(pg - mg) : 0.f, false, sb);

    if (h == 0) {
        float af = pf - (mf + logf(sf));
        float ag = pg - (mg + logf(sg));
        g_kl[i * B_N + j] = expf(ag) * (ag - af);
    }

    // last-block-does-colsum (threadFenceReduction pattern; deterministic)
    __threadfence();
    __syncthreads();
    if (t == 0) s_rank = atomicAdd(&g_sync, 1u);
    __syncthreads();
    if (s_rank == B_N - 1) {
        __threadfence();                   // acquire: all kl rows visible
        float s = 0.f;
#pragma unroll
        for (int k = 0; k < 32; k++)
            s += g_kl[(h * 32 + k) * B_N + j];
        sC[0][h][j] = s;
        __syncthreads();
        if (h == 0)
            out[j] = (sC[0][0][j] + sC[0][1][j]) + (sC[0][2][j] + sC[0][3][j]);
        if (t == 0) g_sync = 0u;           // reset for next graph replay
    }
}

// ---------------------------------------------------------------------------
extern "C" void kernel_launch(void* const* d_in, const int* in_sizes, int n_in,
                              void* d_out, int out_size) {
    const float* img = nullptr;
    const float* lng = nullptr;
    const float* tmp = nullptr;
    for (int i = 0; i < n_in; i++) {
        if (in_sizes[i] == B_N * D_F)      img = (const float*)d_in[i];
        else if (in_sizes[i] == B_N * D_G) lng = (const float*)d_in[i];
        else if (in_sizes[i] == 1)         tmp = (const float*)d_in[i];
    }
    if (!img) img = (const float*)d_in[0];
    if (!lng) lng = (const float*)d_in[1];
    if (!tmp) tmp = (const float*)d_in[2];

    gram_mma<<<NBLK, 256>>>(img, lng);
    rows_colsum<<<B_N, 512>>>(tmp, (float*)d_out);
}